// round 10
// baseline (speedup 1.0000x reference)
#include <cuda_runtime.h>
#include <cuda_fp16.h>
#include <math.h>
#include <math_constants.h>
#include <stdint.h>

// Problem dims
#define Bz  128
#define Nf  196
#define Ez  2048
#define Dz  512
#define Az  512
#define Mz  (Bz*Nf)   // 25088

// GEMM tiling
#define BM  128
#define BN  128
#define TK  32
#define KSTAGES (Ez/TK)   // 64
#define NSTG 3

// SMEM byte layout: A fp32 [3][128][40], B fp16 [3][128][40], red[128] fp32
#define A_STRIDE 40                    // floats per A row (160 B) - conflict-free
#define B_STRIDE 40                    // halves per B row (80 B)  - conflict-free
#define A_STG_B (BM*A_STRIDE*4)        // 20480
#define B_STG_B (BM*B_STRIDE*2)        // 10240
#define OFF_A_B 0
#define OFF_B_B (NSTG*A_STG_B)         // 61440
#define OFF_RED_B (OFF_B_B + NSTG*B_STG_B) // 92160
#define SMEM_BYTES (OFF_RED_B + BM*4)  // 92672

// Scratch (device globals; no allocation allowed)
__device__ float  g_att2[Bz*Az];
__device__ float  g_scores[Mz];
__device__ __half g_WeTH[(size_t)Az*Ez];   // We transposed+fp16: [A][E]

// ---------------------------------------------------------------------------
// PTX helpers (valid for plain sm_103 target)
// ---------------------------------------------------------------------------
__device__ __forceinline__ uint32_t smem_u32(const void* p) {
    uint32_t a;
    asm("{ .reg .u64 t; cvta.to.shared.u64 t, %1; cvt.u32.u64 %0, t; }"
        : "=r"(a) : "l"(p));
    return a;
}

#define CP_ASYNC16(s, g) \
    asm volatile("cp.async.cg.shared.global [%0], [%1], 16;" :: "r"(s), "l"(g))
#define CP_COMMIT() asm volatile("cp.async.commit_group;" ::: "memory")
#define CP_WAIT(n)  asm volatile("cp.async.wait_group %0;" :: "n"(n) : "memory")

// pack two fp32 into f16x2: lo half = x (element k), hi half = y (element k+1)
__device__ __forceinline__ uint32_t pack_h2(float2 v) {
    uint32_t r;
    asm("cvt.rn.f16x2.f32 %0, %1, %2;" : "=r"(r) : "f"(v.y), "f"(v.x));
    return r;
}

__device__ __forceinline__ void mma_f16(float* c, const uint32_t* a,
                                        const uint32_t* b) {
    asm volatile(
        "mma.sync.aligned.m16n8k16.row.col.f32.f16.f16.f32 "
        "{%0,%1,%2,%3}, {%4,%5,%6,%7}, {%8,%9}, {%0,%1,%2,%3};"
        : "+f"(c[0]), "+f"(c[1]), "+f"(c[2]), "+f"(c[3])
        : "r"(a[0]), "r"(a[1]), "r"(a[2]), "r"(a[3]), "r"(b[0]), "r"(b[1]));
}

// ---------------------------------------------------------------------------
// Kernel 0: We [E,A] fp32 -> g_WeTH [A,E] fp16 (transpose + convert)
// ---------------------------------------------------------------------------
__global__ void k_convert_We(const float* __restrict__ We) {
    __shared__ float t[32][33];
    int e0 = blockIdx.x * 32, a0 = blockIdx.y * 32;
    int tx = threadIdx.x, ty = threadIdx.y;   // (32, 8)
    #pragma unroll
    for (int j = 0; j < 32; j += 8)
        t[ty + j][tx] = We[(size_t)(e0 + ty + j) * Az + a0 + tx];
    __syncthreads();
    #pragma unroll
    for (int j = 0; j < 32; j += 8)
        g_WeTH[(size_t)(a0 + ty + j) * Ez + e0 + tx] = __float2half(t[tx][ty + j]);
}

// ---------------------------------------------------------------------------
// Kernel 1: att2[b,a] = dec[b,:] @ Wd[:,a] + bd[a]; also zero g_scores
// ---------------------------------------------------------------------------
__global__ void k_att2(const float* __restrict__ dec,
                       const float* __restrict__ Wd,
                       const float* __restrict__ bd) {
    __shared__ float dec_s[Dz];
    int b = blockIdx.x, tid = threadIdx.x;
    dec_s[tid]       = dec[b*Dz + tid];
    dec_s[tid + 256] = dec[b*Dz + tid + 256];
    __syncthreads();
    for (int a0 = tid; a0 < Az; a0 += 256) {
        float acc = bd[a0];
        #pragma unroll 8
        for (int d = 0; d < Dz; d++) acc += dec_s[d] * Wd[d*Az + a0];
        g_att2[b*Az + a0] = acc;
    }
    for (int k = blockIdx.x*256 + tid; k < Mz; k += gridDim.x*256)
        g_scores[k] = 0.f;
}

// ---------------------------------------------------------------------------
// Kernel 2: fp16 m16n8k16 mma.sync GEMM (fp32 accum) + fused tanh/Wf epilogue
// A: enc fp32 in smem (cp.async), fragments packed to f16x2 in-register.
// B: g_WeTH fp16, [n][k] layout so (k,k+1) are contiguous per fragment reg.
// ---------------------------------------------------------------------------
__global__ __launch_bounds__(256, 2)
void k_gemm(const float* __restrict__ enc,
            const float* __restrict__ be,
            const float* __restrict__ Wf) {
    extern __shared__ char smc[];
    const uint32_t sb = smem_u32(smc);
    const int tid  = threadIdx.x;
    const int lane = tid & 31;
    const int gid  = lane >> 2;      // 0..7
    const int tg   = lane & 3;       // 0..3
    const int wm   = (tid >> 5) & 1; // warp_m (64 rows)
    const int wn   = (tid >> 5) >> 1;// warp_n 0..3 (32 cols)
    const int n0   = blockIdx.x * BN;   // n fastest -> L2 reuse of enc
    const int m0   = blockIdx.y * BM;

    auto load_stage = [&](int ks, int st) {
        const int k0 = ks * TK;
        // A: 128 rows x 32 fp32 = 8 chunks/row, 1024 chunks, 4/thread
        #pragma unroll
        for (int i = 0; i < 4; i++) {
            int f   = tid + i*256;
            int row = f >> 3, kq = f & 7;
            uint32_t dst = sb + OFF_A_B + st*A_STG_B + row*(A_STRIDE*4) + kq*16;
            CP_ASYNC16(dst, enc + (size_t)(m0 + row)*Ez + k0 + kq*4);
        }
        // B: 128 n-rows x 32 fp16 = 4 chunks/row, 512 chunks, 2/thread
        #pragma unroll
        for (int i = 0; i < 2; i++) {
            int f   = tid + i*256;
            int row = f >> 2, kq = f & 3;
            uint32_t dst = sb + OFF_B_B + st*B_STG_B + row*(B_STRIDE*2) + kq*16;
            CP_ASYNC16(dst, g_WeTH + (size_t)(n0 + row)*Ez + k0 + kq*8);
        }
    };

    float acc[4][4][4];
    #pragma unroll
    for (int mt = 0; mt < 4; mt++)
        #pragma unroll
        for (int nt = 0; nt < 4; nt++)
            #pragma unroll
            for (int q = 0; q < 4; q++) acc[mt][nt][q] = 0.f;

    load_stage(0, 0); CP_COMMIT();
    load_stage(1, 1); CP_COMMIT();

    int cur = 0;
    for (int ks = 0; ks < KSTAGES; ks++) {
        if (ks + 2 < KSTAGES) {
            load_stage(ks + 2, (ks + 2) % NSTG);
            CP_COMMIT();
            CP_WAIT(2);
        } else if (ks + 1 < KSTAGES) {
            CP_WAIT(1);
        } else {
            CP_WAIT(0);
        }
        __syncthreads();

        const float*  Af = (const float*)(smc + OFF_A_B + cur*A_STG_B);
        const __half* Bf = (const __half*)(smc + OFF_B_B + cur*B_STG_B);
        #pragma unroll
        for (int kk = 0; kk < 2; kk++) {          // two k16 steps per stage
            const int kb = kk * 16;
            uint32_t af[4][4];
            #pragma unroll
            for (int mt = 0; mt < 4; mt++) {
                const float* Ab = Af + (wm*64 + mt*16 + gid)*A_STRIDE + kb + 2*tg;
                af[mt][0] = pack_h2(*(const float2*)(Ab));
                af[mt][1] = pack_h2(*(const float2*)(Ab + 8*A_STRIDE));
                af[mt][2] = pack_h2(*(const float2*)(Ab + 8));
                af[mt][3] = pack_h2(*(const float2*)(Ab + 8*A_STRIDE + 8));
            }
            uint32_t bfr[4][2];
            #pragma unroll
            for (int nt = 0; nt < 4; nt++) {
                const __half* Bb = Bf + (wn*32 + nt*8 + gid)*B_STRIDE + kb + 2*tg;
                bfr[nt][0] = *(const uint32_t*)(Bb);
                bfr[nt][1] = *(const uint32_t*)(Bb + 8);
            }
            #pragma unroll
            for (int mt = 0; mt < 4; mt++)
                #pragma unroll
                for (int nt = 0; nt < 4; nt++)
                    mma_f16(acc[mt][nt], af[mt], bfr[nt]);
        }
        __syncthreads();
        cur = (cur + 1) % NSTG;
    }

    // Epilogue: v = acc + be[c] + att2[b,c]; p += Wf[c]*tanh(v); reduce rows.
    float* red = (float*)(smc + OFF_RED_B);
    if (tid < BM) red[tid] = 0.f;
    __syncthreads();

    #pragma unroll
    for (int mt = 0; mt < 4; mt++) {
        #pragma unroll
        for (int r2 = 0; r2 < 2; r2++) {
            int mloc = wm*64 + mt*16 + r2*8 + gid;
            int m = m0 + mloc;
            int b = m / Nf;
            const float* at2 = g_att2 + (size_t)b*Az;
            float p = 0.f;
            #pragma unroll
            for (int nt = 0; nt < 4; nt++) {
                #pragma unroll
                for (int cc = 0; cc < 2; cc++) {
                    int c = n0 + wn*32 + nt*8 + 2*tg + cc;
                    float v = acc[mt][nt][r2*2 + cc] + be[c] + at2[c];
                    p += Wf[c] * tanhf(v);
                }
            }
            atomicAdd(&red[mloc], p);
        }
    }
    __syncthreads();
    if (tid < BM) atomicAdd(&g_scores[m0 + tid], red[tid]);
}

// ---------------------------------------------------------------------------
// Kernel 3a: softmax over N per batch
// ---------------------------------------------------------------------------
__global__ void k_softmax(const float* __restrict__ bf,
                          float* __restrict__ alpha_out) {
    const int b = blockIdx.x, tid = threadIdx.x;
    __shared__ float sdata[256];
    float s = (tid < Nf) ? (g_scores[b*Nf + tid] + bf[0]) : -CUDART_INF_F;
    sdata[tid] = s; __syncthreads();
    for (int off = 128; off; off >>= 1) {
        if (tid < off) sdata[tid] = fmaxf(sdata[tid], sdata[tid + off]);
        __syncthreads();
    }
    float mx = sdata[0]; __syncthreads();
    float e = (tid < Nf) ? expf(s - mx) : 0.f;
    sdata[tid] = e; __syncthreads();
    for (int off = 128; off; off >>= 1) {
        if (tid < off) sdata[tid] += sdata[tid + off];
        __syncthreads();
    }
    float inv = 1.f / sdata[0];
    if (tid < Nf) alpha_out[b*Nf + tid] = e * inv;
}

// ---------------------------------------------------------------------------
// Kernel 3b: context[b,e] = sum_n alpha[b,n]*enc[b,n,e]. Unroll 7 (196=7*28)
// for MLP=7; grid (Bz,4) x 128 threads, one float4 column per thread.
// ---------------------------------------------------------------------------
__global__ __launch_bounds__(128)
void k_context(const float* __restrict__ enc,
               const float* __restrict__ alpha,
               float* __restrict__ ctx) {
    const int b  = blockIdx.x;
    const int e4 = blockIdx.y * 128 + threadIdx.x;   // 0..511
    __shared__ float a_s[Nf];
    for (int n = threadIdx.x; n < Nf; n += 128) a_s[n] = alpha[b*Nf + n];
    __syncthreads();
    const float4* p = (const float4*)(enc + (size_t)b*Nf*Ez) + e4;
    float4 s[7];
    #pragma unroll
    for (int i = 0; i < 7; i++) s[i] = make_float4(0.f, 0.f, 0.f, 0.f);
    #pragma unroll 2
    for (int n = 0; n < Nf; n += 7) {
        float4 v[7];
        #pragma unroll
        for (int i = 0; i < 7; i++) v[i] = p[(size_t)(n + i)*(Ez/4)];
        #pragma unroll
        for (int i = 0; i < 7; i++) {
            float a = a_s[n + i];
            s[i].x += a*v[i].x; s[i].y += a*v[i].y;
            s[i].z += a*v[i].z; s[i].w += a*v[i].w;
        }
    }
    float4 r = s[0];
    #pragma unroll
    for (int i = 1; i < 7; i++) {
        r.x += s[i].x; r.y += s[i].y; r.z += s[i].z; r.w += s[i].w;
    }
    ((float4*)ctx)[(size_t)b*(Ez/4) + e4] = r;
}

// ---------------------------------------------------------------------------
// kernel_launch: inputs in metadata order:
// 0 encoder_out [B,N,E], 1 decoder_hidden [B,D], 2 We [E,A], 3 be [A],
// 4 Wd [D,A], 5 bd [A], 6 Wf [A,1], 7 bf [1]
// output: context [B,E] then alpha [B,N,1], concatenated fp32
// ---------------------------------------------------------------------------
extern "C" void kernel_launch(void* const* d_in, const int* in_sizes, int n_in,
                              void* d_out, int out_size) {
    const float* enc = (const float*)d_in[0];
    const float* dec = (const float*)d_in[1];
    const float* We  = (const float*)d_in[2];
    const float* be  = (const float*)d_in[3];
    const float* Wd  = (const float*)d_in[4];
    const float* bd  = (const float*)d_in[5];
    const float* Wf  = (const float*)d_in[6];
    const float* bf  = (const float*)d_in[7];

    float* out   = (float*)d_out;
    float* ctx   = out;                 // [B, E]
    float* alpha = out + (size_t)Bz*Ez; // [B, N]

    static bool attr_set = false;
    if (!attr_set) {
        cudaFuncSetAttribute(k_gemm, cudaFuncAttributeMaxDynamicSharedMemorySize,
                             SMEM_BYTES);
        attr_set = true;
    }

    k_convert_We<<<dim3(Ez/32, Az/32), dim3(32, 8)>>>(We);
    k_att2<<<Bz, 256>>>(dec, Wd, bd);
    k_gemm<<<dim3(Az/BN, Mz/BM), 256, SMEM_BYTES>>>(enc, be, Wf);
    k_softmax<<<Bz, 256>>>(bf, alpha);
    k_context<<<dim3(Bz, 4), 128>>>(enc, alpha, ctx);
}